// round 14
// baseline (speedup 1.0000x reference)
#include <cuda_runtime.h>
#include <cuda_bf16.h>
#include <cstdint>

#define HH 512
#define WW 512
#define BATCH 32
#define THREADS 128
#define OUTW 256          // output cols per tile (2 per thread)
#define OUTH 16           // output rows per tile
#define SPITCH 264        // smem row pitch (floats): 4 left halo + 256 + 4 right
#define TILE_H (OUTH + 6) // 22 logical rows
#define SLOTS 14          // resident smem rows (each row read exactly once)
#define NCHX 66           // 16-byte chunks per row per map

typedef unsigned long long u64;

__device__ double g_acc = 0.0;
__device__ unsigned int g_tick = 0;

// ---- packed f32x2 helpers ----
static __device__ __forceinline__ u64 fma2_(u64 a, u64 b, u64 c) {
    u64 d; asm("fma.rn.f32x2 %0,%1,%2,%3;" : "=l"(d) : "l"(a), "l"(b), "l"(c)); return d;
}
static __device__ __forceinline__ u64 mul2_(u64 a, u64 b) {
    u64 d; asm("mul.rn.f32x2 %0,%1,%2;" : "=l"(d) : "l"(a), "l"(b)); return d;
}
static __device__ __forceinline__ u64 add2_(u64 a, u64 b) {
    u64 d; asm("add.rn.f32x2 %0,%1,%2;" : "=l"(d) : "l"(a), "l"(b)); return d;
}
static __device__ __forceinline__ u64 pk2(float lo, float hi) {
    u64 r; asm("mov.b64 %0,{%1,%2};" : "=l"(r) : "f"(lo), "f"(hi)); return r;
}
static __device__ __forceinline__ void upk2(u64 v, float& lo, float& hi) {
    asm("mov.b64 {%0,%1},%2;" : "=f"(lo), "=f"(hi) : "l"(v));
}
static __device__ __forceinline__ u64 neg2_(u64 a) { return a ^ 0x8000000080000000ULL; }
// pair {hi(a), lo(b)} — register re-pairing only
static __device__ __forceinline__ u64 sh2_(u64 a, u64 b) {
    unsigned al, ah, bl, bh;
    asm("mov.b64 {%0,%1},%2;" : "=r"(al), "=r"(ah) : "l"(a));
    asm("mov.b64 {%0,%1},%2;" : "=r"(bl), "=r"(bh) : "l"(b));
    u64 r;
    asm("mov.b64 %0,{%1,%2};" : "=l"(r) : "r"(ah), "r"(bl));
    return r;
}
static __device__ __forceinline__ float rcpa_(float a) {
    float r; asm("rcp.approx.f32 %0,%1;" : "=f"(r) : "f"(a)); return r;
}

static __device__ __forceinline__ void cp16(unsigned saddr, const float* gaddr, int srcsz) {
    asm volatile("cp.async.cg.shared.global [%0], [%1], 16, %2;"
                 :: "r"(saddr), "l"(gaddr), "r"(srcsz));
}

__global__ __launch_bounds__(THREADS, 5) void ssim_main(const float* __restrict__ xg,
                                                        const float* __restrict__ yg,
                                                        const float* __restrict__ kern,
                                                        float* __restrict__ out,
                                                        int nblocks)
{
    __shared__ float sx[SLOTS][SPITCH];
    __shared__ float sy[SLOTS][SPITCH];
    __shared__ float wsum[4];

    const int tid  = threadIdx.x;
    const int col0 = blockIdx.x * OUTW;
    const int row0 = blockIdx.y * OUTH;
    const long base = (long)blockIdx.z * (HH * WW);

    // separable 1-D weights: v_i = sqrt(k[i][i])
    u64 w2[7];
#pragma unroll
    for (int t = 0; t < 7; t++) {
        float wt = sqrtf(__ldg(kern + t * 7 + t));
        w2[t] = pk2(wt, wt);
    }

    // ---- division-free staging descriptors ----
    // Row has 132 16B chunks: 66 x-map, 66 y-map. Thread tid owns chunk tid;
    // threads 0..3 also own chunk 128+tid (y map, col chunk 62+tid, col-checked).
    // smem col s <-> global col (col0 - 4 + s); logical row r <-> global row row0-3+r.
    const int  m0   = tid >= NCHX;
    const int  cc0  = tid - (m0 ? NCHX : 0);
    const int  gc0  = col0 - 4 + 4 * cc0;
    const bool ok0  = (gc0 >= 0) && (gc0 < WW);
    const float* gp0 = m0 ? yg : xg;
    const long goff0 = base + gc0;
    const unsigned sd0 = (unsigned)__cvta_generic_to_shared(
        (m0 ? sy[0] : sx[0]) + 4 * cc0);

    const int  cc1  = 62 + tid;                       // used when tid < 4
    const int  gc1  = col0 - 4 + 4 * cc1;
    const bool ok1  = (gc1 >= 0) && (gc1 < WW);
    const long goff1 = base + gc1;
    const unsigned sd1 = (unsigned)__cvta_generic_to_shared(sy[0] + 4 * cc1);

    // stage logical rows [R0, R0+N) into smem slots [S0, S0+N)
#define STAGE_ROWS(R0, N, S0)                                                  \
    {                                                                          \
        _Pragma("unroll")                                                      \
        for (int rr = 0; rr < (N); rr++) {                                     \
            const int gr_ = row0 - 3 + (R0) + rr;                              \
            const bool rok_ = ((unsigned)gr_ < HH);                            \
            const unsigned so_ = ((S0) + rr) * (SPITCH * 4);                   \
            const bool o0_ = ok0 && rok_;                                      \
            cp16(sd0 + so_, o0_ ? (gp0 + goff0 + (long)gr_ * WW) : xg,         \
                 o0_ ? 16 : 0);                                                \
            if (tid < 4) {                                                     \
                const bool o1_ = ok1 && rok_;                                  \
                cp16(sd1 + so_, o1_ ? (yg + goff1 + (long)gr_ * WW) : xg,      \
                     o1_ ? 16 : 0);                                            \
            }                                                                  \
        }                                                                      \
    }

    const u64 two2 = pk2(2.f, 2.f);
    const u64 c1_2 = pk2(1e-4f, 1e-4f);
    const u64 c2_2 = pk2(9e-4f, 9e-4f);

    u64 Wx[7], Wy[7], Wxx[7], Wyy[7], Wxy[7];
    float sum = 0.f;

    // horizontal 7-tap conv of (x,y,xx,yy,xy) on smem slot sl -> window slot s
#define HCONV(sl, s)                                                         \
    {                                                                        \
        const float* rx_ = &sx[(sl)][2 * tid];                               \
        const float* ry_ = &sy[(sl)][2 * tid];                               \
        u64 e0 = *(const u64*)(rx_ + 0), e1 = *(const u64*)(rx_ + 2);        \
        u64 e2 = *(const u64*)(rx_ + 4), e3 = *(const u64*)(rx_ + 6);        \
        u64 e4 = *(const u64*)(rx_ + 8);                                     \
        u64 f0 = *(const u64*)(ry_ + 0), f1 = *(const u64*)(ry_ + 2);        \
        u64 f2 = *(const u64*)(ry_ + 4), f3 = *(const u64*)(ry_ + 6);        \
        u64 f4 = *(const u64*)(ry_ + 8);                                     \
        u64 xp[7] = {sh2_(e0, e1), e1, sh2_(e1, e2), e2,                     \
                     sh2_(e2, e3), e3, sh2_(e3, e4)};                        \
        u64 yp[7] = {sh2_(f0, f1), f1, sh2_(f1, f2), f2,                     \
                     sh2_(f2, f3), f3, sh2_(f3, f4)};                        \
        u64 wx0 = mul2_(w2[0], xp[0]);                                       \
        u64 wy0 = mul2_(w2[0], yp[0]);                                       \
        u64 a_ = wx0, b_ = wy0;                                              \
        u64 cxx_ = mul2_(wx0, xp[0]);                                        \
        u64 cyy_ = mul2_(wy0, yp[0]);                                        \
        u64 cxy_ = mul2_(wx0, yp[0]);                                        \
        _Pragma("unroll")                                                    \
        for (int t = 1; t < 7; t++) {                                        \
            u64 wx = mul2_(w2[t], xp[t]);                                    \
            u64 wy = mul2_(w2[t], yp[t]);                                    \
            a_   = add2_(a_, wx);                                            \
            b_   = add2_(b_, wy);                                            \
            cxx_ = fma2_(wx, xp[t], cxx_);                                   \
            cyy_ = fma2_(wy, yp[t], cyy_);                                   \
            cxy_ = fma2_(wx, yp[t], cxy_);                                   \
        }                                                                    \
        Wx[(s)] = a_; Wy[(s)] = b_;                                          \
        Wxx[(s)] = cxx_; Wyy[(s)] = cyy_; Wxy[(s)] = cxy_;                   \
    }

    // vertical conv + SSIM for output row ending at logical row r
#define VROW(r)                                                              \
    {                                                                        \
        u64 mx  = mul2_(w2[0], Wx[((r) - 6) % 7]);                           \
        u64 my  = mul2_(w2[0], Wy[((r) - 6) % 7]);                           \
        u64 exx = mul2_(w2[0], Wxx[((r) - 6) % 7]);                          \
        u64 eyy = mul2_(w2[0], Wyy[((r) - 6) % 7]);                          \
        u64 exy = mul2_(w2[0], Wxy[((r) - 6) % 7]);                          \
        _Pragma("unroll")                                                    \
        for (int t = 1; t < 7; t++) {                                        \
            int s = ((r) - 6 + t) % 7;                                       \
            mx  = fma2_(w2[t], Wx[s],  mx);                                  \
            my  = fma2_(w2[t], Wy[s],  my);                                  \
            exx = fma2_(w2[t], Wxx[s], exx);                                 \
            eyy = fma2_(w2[t], Wyy[s], eyy);                                 \
            exy = fma2_(w2[t], Wxy[s], exy);                                 \
        }                                                                    \
        u64 nmx = neg2_(mx);                                                 \
        u64 sxx = fma2_(nmx, mx, exx);                                       \
        u64 syy = fma2_(neg2_(my), my, eyy);                                 \
        u64 sxy = fma2_(nmx, my, exy);                                       \
        u64 mxmy = mul2_(mx, my);                                            \
        u64 n1 = fma2_(two2, mxmy, c1_2);                                    \
        u64 n2 = fma2_(two2, sxy, c2_2);                                     \
        u64 num = mul2_(n1, n2);                                             \
        u64 myy = mul2_(my, my);                                             \
        u64 d1 = fma2_(mx, mx, myy);                                         \
        d1 = add2_(d1, c1_2);                                                \
        u64 d2 = add2_(add2_(sxx, syy), c2_2);                               \
        u64 den = mul2_(d1, d2);                                             \
        float nlo, nhi, dlo, dhi;                                            \
        upk2(num, nlo, nhi);                                                 \
        upk2(den, dlo, dhi);                                                 \
        float dd = dlo * dhi;                                                \
        float nn = fmaf(nlo, dhi, nhi * dlo);                                \
        sum = fmaf(nn, rcpa_(dd), sum);                                      \
    }

    // ---- phase A: rows 0..13 resident ----
    STAGE_ROWS(0, SLOTS, 0);
    asm volatile("cp.async.commit_group;");
    asm volatile("cp.async.wait_group 0;");
    __syncthreads();

    // prologue rows 0..5
#pragma unroll
    for (int r = 0; r < 6; r++) {
        HCONV(r, r);
    }
    // rows 6..7 (outputs)
#pragma unroll
    for (int r = 6; r < 8; r++) {
        HCONV(r, r % 7);
        VROW(r);
    }

    // all warps have consumed slots 0..7 -> refill them with rows 14..21
    __syncthreads();
    STAGE_ROWS(14, 8, 0);
    asm volatile("cp.async.commit_group;");

    // rows 8..13 (outputs) — overlapped with phase-B loads
#pragma unroll
    for (int r = 8; r < 14; r++) {
        HCONV(r, r % 7);
        VROW(r);
    }

    asm volatile("cp.async.wait_group 0;");
    __syncthreads();

    // rows 14..21 (outputs) from slots 0..7
#pragma unroll
    for (int r = 14; r < TILE_H; r++) {
        HCONV(r - 14, r % 7);
        VROW(r);
    }
#undef HCONV
#undef VROW
#undef STAGE_ROWS

    // ---- block reduction ----
#pragma unroll
    for (int off = 16; off; off >>= 1)
        sum += __shfl_down_sync(0xffffffffu, sum, off);
    if ((tid & 31) == 0) wsum[tid >> 5] = sum;
    __syncthreads();

    // ---- last-block finalize (single-kernel) ----
    if (tid == 0) {
        float s = wsum[0] + wsum[1] + wsum[2] + wsum[3];
        atomicAdd(&g_acc, (double)s);
        __threadfence();
        unsigned t = atomicAdd(&g_tick, 1u);
        if (t == (unsigned)(nblocks - 1)) {
            double v = *(volatile double*)&g_acc;
            out[0] = (float)(v / ((double)BATCH * HH * WW));
            g_acc = 0.0;          // reset for next graph replay
            g_tick = 0;
            __threadfence();
        }
    }
}

extern "C" void kernel_launch(void* const* d_in, const int* in_sizes, int n_in,
                              void* d_out, int out_size)
{
    const float* x = (const float*)d_in[0];
    const float* y = (const float*)d_in[1];
    const float* k = (const float*)d_in[2];
    float* out = (float*)d_out;

    dim3 grid(WW / OUTW, HH / OUTH, BATCH);
    int nblocks = grid.x * grid.y * grid.z;
    ssim_main<<<grid, THREADS>>>(x, y, k, out, nblocks);
}

// round 15
// speedup vs baseline: 1.0320x; 1.0320x over previous
#include <cuda_runtime.h>
#include <cuda_bf16.h>
#include <cstdint>

#define HH 512
#define WW 512
#define BATCH 32
#define THREADS 128
#define OUTW 256          // output cols per tile (2 per thread)
#define OUTH 16           // output rows per tile
#define SPITCH 264        // smem row pitch (floats): 4 left halo + 256 + 4 right
#define TILE_H (OUTH + 6) // 22
#define NCH 66            // 16-byte chunks per row per map
#define ROWS_A 14         // staging group A rows (0..13)

typedef unsigned long long u64;

__device__ double g_acc = 0.0;
__device__ unsigned int g_tick = 0;

// ---- packed f32x2 helpers ----
static __device__ __forceinline__ u64 fma2_(u64 a, u64 b, u64 c) {
    u64 d; asm("fma.rn.f32x2 %0,%1,%2,%3;" : "=l"(d) : "l"(a), "l"(b), "l"(c)); return d;
}
static __device__ __forceinline__ u64 mul2_(u64 a, u64 b) {
    u64 d; asm("mul.rn.f32x2 %0,%1,%2;" : "=l"(d) : "l"(a), "l"(b)); return d;
}
static __device__ __forceinline__ u64 add2_(u64 a, u64 b) {
    u64 d; asm("add.rn.f32x2 %0,%1,%2;" : "=l"(d) : "l"(a), "l"(b)); return d;
}
static __device__ __forceinline__ u64 pk2(float lo, float hi) {
    u64 r; asm("mov.b64 %0,{%1,%2};" : "=l"(r) : "f"(lo), "f"(hi)); return r;
}
static __device__ __forceinline__ void upk2(u64 v, float& lo, float& hi) {
    asm("mov.b64 {%0,%1},%2;" : "=f"(lo), "=f"(hi) : "l"(v));
}
static __device__ __forceinline__ u64 neg2_(u64 a) { return a ^ 0x8000000080000000ULL; }
// pair {hi(a), lo(b)} — register re-pairing only
static __device__ __forceinline__ u64 sh2_(u64 a, u64 b) {
    unsigned al, ah, bl, bh;
    asm("mov.b64 {%0,%1},%2;" : "=r"(al), "=r"(ah) : "l"(a));
    asm("mov.b64 {%0,%1},%2;" : "=r"(bl), "=r"(bh) : "l"(b));
    u64 r;
    asm("mov.b64 %0,{%1,%2};" : "=l"(r) : "r"(ah), "r"(bl));
    return r;
}

static __device__ __forceinline__ void cp16(unsigned saddr, const float* gaddr, int srcsz) {
    asm volatile("cp.async.cg.shared.global [%0], [%1], 16, %2;"
                 :: "r"(saddr), "l"(gaddr), "r"(srcsz));
}

// Gaussian window is symmetric: w[6-t] == w[t]; keep only 4 packed weights.
#define WT(t) w2[(t) < 4 ? (t) : 6 - (t)]

struct RowBuf { u64 e0, e1, e2, e3, e4, f0, f1, f2, f3, f4; };

__global__ __launch_bounds__(THREADS, 4) void ssim_main(const float* __restrict__ xg,
                                                        const float* __restrict__ yg,
                                                        const float* __restrict__ kern,
                                                        float* __restrict__ out,
                                                        int nblocks)
{
    extern __shared__ float smem_dyn[];
    float (*sx)[SPITCH] = (float (*)[SPITCH])smem_dyn;
    float (*sy)[SPITCH] = (float (*)[SPITCH])(smem_dyn + TILE_H * SPITCH);
    __shared__ float wsum[4];

    const int tid  = threadIdx.x;
    const int col0 = blockIdx.x * OUTW;
    const int row0 = blockIdx.y * OUTH;
    const long base = (long)blockIdx.z * (HH * WW);

    // separable 1-D weights: v_i = sqrt(k[i][i]); symmetric -> 4 distinct
    u64 w2[4];
#pragma unroll
    for (int t = 0; t < 4; t++) {
        float wt = sqrtf(__ldg(kern + t * 7 + t));
        w2[t] = pk2(wt, wt);
    }

    // ---- stage tile via cp.async 16B chunks, TWO commit groups ----
    // smem col s <-> global col (col0 - 4 + s); row r <-> global row (row0 - 3 + r).
    // col0 in {0,256} => every chunk fully in-image or fully out (clean zfill).
#define STAGE_RANGE(RLO, RHI)                                                 \
    for (int i = tid; i < ((RHI) - (RLO)) * NCH; i += THREADS) {              \
        int r  = (RLO) + i / NCH;                                             \
        int j  = i % NCH;                                                     \
        int gr = row0 - 3 + r;                                                \
        int gc = col0 - 4 + 4 * j;                                            \
        bool ok = ((unsigned)gr < HH) && (gc >= 0) && (gc < WW);              \
        long gi = base + (long)gr * WW + gc;                                  \
        const float* srcx = ok ? (xg + gi) : xg;                              \
        const float* srcy = ok ? (yg + gi) : yg;                              \
        int sz = ok ? 16 : 0;                                                 \
        cp16((unsigned)__cvta_generic_to_shared(sx[r] + 4 * j), srcx, sz);    \
        cp16((unsigned)__cvta_generic_to_shared(sy[r] + 4 * j), srcy, sz);    \
    }

    STAGE_RANGE(0, ROWS_A)
    asm volatile("cp.async.commit_group;");
    STAGE_RANGE(ROWS_A, TILE_H)
    asm volatile("cp.async.commit_group;");
    asm volatile("cp.async.wait_group 1;");   // group A resident; B still in flight
    __syncthreads();

    const u64 two2 = pk2(2.f, 2.f);
    const u64 c1_2 = pk2(1e-4f, 1e-4f);
    const u64 c2_2 = pk2(9e-4f, 9e-4f);

    u64 Wx[7], Wy[7], Wxx[7], Wyy[7], Wxy[7];
    float sum = 0.f;

    RowBuf A, B;

    // load smem row r into register buffer (10 aligned LDS.64)
#define PRELOAD(Buf, r)                                                      \
    {                                                                        \
        const float* rx_ = &sx[(r)][2 * tid];                                \
        const float* ry_ = &sy[(r)][2 * tid];                                \
        Buf.e0 = *(const u64*)(rx_ + 0); Buf.e1 = *(const u64*)(rx_ + 2);    \
        Buf.e2 = *(const u64*)(rx_ + 4); Buf.e3 = *(const u64*)(rx_ + 6);    \
        Buf.e4 = *(const u64*)(rx_ + 8);                                     \
        Buf.f0 = *(const u64*)(ry_ + 0); Buf.f1 = *(const u64*)(ry_ + 2);    \
        Buf.f2 = *(const u64*)(ry_ + 4); Buf.f3 = *(const u64*)(ry_ + 6);    \
        Buf.f4 = *(const u64*)(ry_ + 8);                                     \
    }

    // horizontal 7-tap conv of (x,y,xx,yy,xy) from register buffer -> window slot s
#define HCONV_R(Buf, s)                                                      \
    {                                                                        \
        u64 xp[7] = {sh2_(Buf.e0, Buf.e1), Buf.e1, sh2_(Buf.e1, Buf.e2),     \
                     Buf.e2, sh2_(Buf.e2, Buf.e3), Buf.e3,                   \
                     sh2_(Buf.e3, Buf.e4)};                                  \
        u64 yp[7] = {sh2_(Buf.f0, Buf.f1), Buf.f1, sh2_(Buf.f1, Buf.f2),     \
                     Buf.f2, sh2_(Buf.f2, Buf.f3), Buf.f3,                   \
                     sh2_(Buf.f3, Buf.f4)};                                  \
        u64 wx0 = mul2_(WT(0), xp[0]);                                       \
        u64 wy0 = mul2_(WT(0), yp[0]);                                       \
        u64 a_ = wx0, b_ = wy0;                                              \
        u64 cxx_ = mul2_(wx0, xp[0]);                                        \
        u64 cyy_ = mul2_(wy0, yp[0]);                                        \
        u64 cxy_ = mul2_(wx0, yp[0]);                                        \
        _Pragma("unroll")                                                    \
        for (int t = 1; t < 7; t++) {                                        \
            u64 wx = mul2_(WT(t), xp[t]);                                    \
            u64 wy = mul2_(WT(t), yp[t]);                                    \
            a_   = add2_(a_, wx);                                            \
            b_   = add2_(b_, wy);                                            \
            cxx_ = fma2_(wx, xp[t], cxx_);                                   \
            cyy_ = fma2_(wy, yp[t], cyy_);                                   \
            cxy_ = fma2_(wx, yp[t], cxy_);                                   \
        }                                                                    \
        Wx[(s)] = a_; Wy[(s)] = b_;                                          \
        Wxx[(s)] = cxx_; Wyy[(s)] = cyy_; Wxy[(s)] = cxy_;                   \
    }

    // vertical conv + SSIM for output row ending at logical row r
#define VROW(r)                                                              \
    {                                                                        \
        u64 mx  = mul2_(WT(0), Wx[((r) - 6) % 7]);                           \
        u64 my  = mul2_(WT(0), Wy[((r) - 6) % 7]);                           \
        u64 exx = mul2_(WT(0), Wxx[((r) - 6) % 7]);                          \
        u64 eyy = mul2_(WT(0), Wyy[((r) - 6) % 7]);                          \
        u64 exy = mul2_(WT(0), Wxy[((r) - 6) % 7]);                          \
        _Pragma("unroll")                                                    \
        for (int t = 1; t < 7; t++) {                                        \
            int s = ((r) - 6 + t) % 7;                                       \
            mx  = fma2_(WT(t), Wx[s],  mx);                                  \
            my  = fma2_(WT(t), Wy[s],  my);                                  \
            exx = fma2_(WT(t), Wxx[s], exx);                                 \
            eyy = fma2_(WT(t), Wyy[s], eyy);                                 \
            exy = fma2_(WT(t), Wxy[s], exy);                                 \
        }                                                                    \
        u64 nmx = neg2_(mx);                                                 \
        u64 sxx = fma2_(nmx, mx, exx);                                       \
        u64 syy = fma2_(neg2_(my), my, eyy);                                 \
        u64 sxy = fma2_(nmx, my, exy);                                       \
        u64 mxmy = mul2_(mx, my);                                            \
        u64 n1 = fma2_(two2, mxmy, c1_2);                                    \
        u64 n2 = fma2_(two2, sxy, c2_2);                                     \
        u64 num = mul2_(n1, n2);                                             \
        u64 myy = mul2_(my, my);                                             \
        u64 d1 = fma2_(mx, mx, myy);                                         \
        d1 = add2_(d1, c1_2);                                                \
        u64 d2 = add2_(add2_(sxx, syy), c2_2);                               \
        u64 den = mul2_(d1, d2);                                             \
        float nlo, nhi, dlo, dhi;                                            \
        upk2(num, nlo, nhi);                                                 \
        upk2(den, dlo, dhi);                                                 \
        sum += __fdividef(nlo, dlo) + __fdividef(nhi, dhi);                  \
    }

    // pipelined compute: preload row r+1's smem data before row r's FMA burst
#pragma unroll
    for (int r = 0; r < TILE_H; r++) {
        if (r == ROWS_A) {                         // group B must be resident now
            asm volatile("cp.async.wait_group 0;");
            __syncthreads();
        }
        if (r == 0 || r == ROWS_A) {
            PRELOAD(A, r);                         // phase start: fill current buffer
        }
        if (r + 1 < TILE_H && r + 1 != ROWS_A) {   // prefetch next row in-phase
            if (r & 1) { PRELOAD(A, r + 1); } else { PRELOAD(B, r + 1); }
        }
        if (r & 1) { HCONV_R(B, r % 7); } else { HCONV_R(A, r % 7); }
        if (r >= 6) VROW(r);
    }
#undef HCONV_R
#undef VROW
#undef PRELOAD
#undef STAGE_RANGE

    // ---- block reduction ----
#pragma unroll
    for (int off = 16; off; off >>= 1)
        sum += __shfl_down_sync(0xffffffffu, sum, off);
    if ((tid & 31) == 0) wsum[tid >> 5] = sum;
    __syncthreads();

    // ---- last-block finalize (single-kernel) ----
    if (tid == 0) {
        float s = wsum[0] + wsum[1] + wsum[2] + wsum[3];
        atomicAdd(&g_acc, (double)s);
        __threadfence();
        unsigned t = atomicAdd(&g_tick, 1u);
        if (t == (unsigned)(nblocks - 1)) {
            double v = *(volatile double*)&g_acc;
            out[0] = (float)(v / ((double)BATCH * HH * WW));
            g_acc = 0.0;          // reset for next graph replay
            g_tick = 0;
            __threadfence();
        }
    }
}

extern "C" void kernel_launch(void* const* d_in, const int* in_sizes, int n_in,
                              void* d_out, int out_size)
{
    const float* x = (const float*)d_in[0];
    const float* y = (const float*)d_in[1];
    const float* k = (const float*)d_in[2];
    float* out = (float*)d_out;

    static int configured = 0;
    const int smem_bytes = 2 * TILE_H * SPITCH * (int)sizeof(float);
    if (!configured) {
        cudaFuncSetAttribute(ssim_main, cudaFuncAttributeMaxDynamicSharedMemorySize,
                             smem_bytes);
        configured = 1;
    }

    dim3 grid(WW / OUTW, HH / OUTH, BATCH);
    int nblocks = grid.x * grid.y * grid.z;
    ssim_main<<<grid, THREADS, smem_bytes>>>(x, y, k, out, nblocks);
}

// round 16
// speedup vs baseline: 1.0824x; 1.0489x over previous
#include <cuda_runtime.h>
#include <cuda_bf16.h>
#include <cstdint>

#define HH 512
#define WW 512
#define BATCH 32
#define THREADS 128
#define OUTW 256          // output cols per tile (2 per thread)
#define OUTH 16           // output rows per tile
#define SPITCH 264        // smem row pitch (floats): 4 left halo + 256 + 4 right
#define TILE_H (OUTH + 6) // 22
#define NCH 66            // 16-byte chunks per row per map (264 floats / 4)
#define ROWS_A 14         // staging group A rows

typedef unsigned long long u64;

__device__ double g_acc = 0.0;
__device__ unsigned int g_tick = 0;

// ---- packed f32x2 helpers ----
static __device__ __forceinline__ u64 fma2_(u64 a, u64 b, u64 c) {
    u64 d; asm("fma.rn.f32x2 %0,%1,%2,%3;" : "=l"(d) : "l"(a), "l"(b), "l"(c)); return d;
}
static __device__ __forceinline__ u64 mul2_(u64 a, u64 b) {
    u64 d; asm("mul.rn.f32x2 %0,%1,%2;" : "=l"(d) : "l"(a), "l"(b)); return d;
}
static __device__ __forceinline__ u64 add2_(u64 a, u64 b) {
    u64 d; asm("add.rn.f32x2 %0,%1,%2;" : "=l"(d) : "l"(a), "l"(b)); return d;
}
static __device__ __forceinline__ u64 pk2(float lo, float hi) {
    u64 r; asm("mov.b64 %0,{%1,%2};" : "=l"(r) : "f"(lo), "f"(hi)); return r;
}
static __device__ __forceinline__ void upk2(u64 v, float& lo, float& hi) {
    asm("mov.b64 {%0,%1},%2;" : "=f"(lo), "=f"(hi) : "l"(v));
}
static __device__ __forceinline__ u64 neg2_(u64 a) { return a ^ 0x8000000080000000ULL; }
// pair {hi(a), lo(b)} — register re-pairing only (no shifts)
static __device__ __forceinline__ u64 sh2_(u64 a, u64 b) {
    unsigned al, ah, bl, bh;
    asm("mov.b64 {%0,%1},%2;" : "=r"(al), "=r"(ah) : "l"(a));
    asm("mov.b64 {%0,%1},%2;" : "=r"(bl), "=r"(bh) : "l"(b));
    u64 r;
    asm("mov.b64 %0,{%1,%2};" : "=l"(r) : "r"(ah), "r"(bl));
    return r;
}

static __device__ __forceinline__ void cp16(unsigned saddr, const float* gaddr, int srcsz) {
    asm volatile("cp.async.cg.shared.global [%0], [%1], 16, %2;"
                 :: "r"(saddr), "l"(gaddr), "r"(srcsz));
}

__global__ __launch_bounds__(THREADS) void ssim_main(const float* __restrict__ x,
                                                     const float* __restrict__ y,
                                                     const float* __restrict__ kern,
                                                     float* __restrict__ out,
                                                     int nblocks)
{
    extern __shared__ float smem_dyn[];
    float (*sx)[SPITCH] = (float (*)[SPITCH])smem_dyn;
    float (*sy)[SPITCH] = (float (*)[SPITCH])(smem_dyn + TILE_H * SPITCH);
    __shared__ float wsum[4];

    const int tid  = threadIdx.x;
    const int col0 = blockIdx.x * OUTW;
    const int row0 = blockIdx.y * OUTH;
    const long base = (long)blockIdx.z * (HH * WW);

    // separable 1-D weights: v_i = sqrt(k[i][i])
    u64 w2[7];
#pragma unroll
    for (int t = 0; t < 7; t++) {
        float wt = sqrtf(__ldg(kern + t * 7 + t));
        w2[t] = pk2(wt, wt);
    }

    // ---- stage x,y tile via cp.async 16B chunks, TWO commit groups ----
    // Group A = rows 0..13, group B = rows 14..21. Compute starts when A lands;
    // B's DRAM latency hides under the first 14 rows of compute.
    // smem col s <-> global col (col0 - 4 + s); row r <-> global row (row0 - 3 + r).
    // col0 in {0,256} => every chunk fully in-image or fully out (clean zfill).
    for (int i = tid; i < ROWS_A * NCH; i += THREADS) {
        int r  = i / NCH;
        int j  = i - r * NCH;
        int gr = row0 - 3 + r;
        int gc = col0 - 4 + 4 * j;
        bool ok = (gr >= 0) && (gr < HH) && (gc >= 0) && (gc < WW);
        long gi = base + (long)gr * WW + gc;
        const float* srcx = ok ? (x + gi) : x;
        const float* srcy = ok ? (y + gi) : y;
        int sz = ok ? 16 : 0;
        cp16((unsigned)__cvta_generic_to_shared(sx[r] + 4 * j), srcx, sz);
        cp16((unsigned)__cvta_generic_to_shared(sy[r] + 4 * j), srcy, sz);
    }
    asm volatile("cp.async.commit_group;");
    for (int i = tid; i < (TILE_H - ROWS_A) * NCH; i += THREADS) {
        int r  = ROWS_A + i / NCH;
        int j  = i % NCH;
        int gr = row0 - 3 + r;
        int gc = col0 - 4 + 4 * j;
        bool ok = (gr < HH) && (gc >= 0) && (gc < WW);   // gr >= 11 here, no low check
        long gi = base + (long)gr * WW + gc;
        const float* srcx = ok ? (x + gi) : x;
        const float* srcy = ok ? (y + gi) : y;
        int sz = ok ? 16 : 0;
        cp16((unsigned)__cvta_generic_to_shared(sx[r] + 4 * j), srcx, sz);
        cp16((unsigned)__cvta_generic_to_shared(sy[r] + 4 * j), srcy, sz);
    }
    asm volatile("cp.async.commit_group;");
    asm volatile("cp.async.wait_group 1;");   // group A resident; B in flight
    __syncthreads();

    const u64 two2 = pk2(2.f, 2.f);
    const u64 c1_2 = pk2(1e-4f, 1e-4f);
    const u64 c2_2 = pk2(9e-4f, 9e-4f);

    u64 Wx[7], Wy[7], Wxx[7], Wyy[7], Wxy[7];
    float sum = 0.f;

    // horizontal 7-tap conv of (x,y,xx,yy,xy); outputs packed pair for global
    // cols (col0+2tid, col0+2tid+1). Aligned LDS.64 at smem cols 2tid..2tid+9.
#define HCONV(r, s)                                                          \
    {                                                                        \
        const float* rx_ = &sx[(r)][2 * tid];                                \
        const float* ry_ = &sy[(r)][2 * tid];                                \
        u64 e0 = *(const u64*)(rx_ + 0), e1 = *(const u64*)(rx_ + 2);        \
        u64 e2 = *(const u64*)(rx_ + 4), e3 = *(const u64*)(rx_ + 6);        \
        u64 e4 = *(const u64*)(rx_ + 8);                                     \
        u64 f0 = *(const u64*)(ry_ + 0), f1 = *(const u64*)(ry_ + 2);        \
        u64 f2 = *(const u64*)(ry_ + 4), f3 = *(const u64*)(ry_ + 6);        \
        u64 f4 = *(const u64*)(ry_ + 8);                                     \
        u64 xp[7] = {sh2_(e0, e1), e1, sh2_(e1, e2), e2,                     \
                     sh2_(e2, e3), e3, sh2_(e3, e4)};                        \
        u64 yp[7] = {sh2_(f0, f1), f1, sh2_(f1, f2), f2,                     \
                     sh2_(f2, f3), f3, sh2_(f3, f4)};                        \
        u64 wx0 = mul2_(w2[0], xp[0]);                                       \
        u64 wy0 = mul2_(w2[0], yp[0]);                                       \
        u64 a_ = wx0, b_ = wy0;                                              \
        u64 cxx_ = mul2_(wx0, xp[0]);                                        \
        u64 cyy_ = mul2_(wy0, yp[0]);                                        \
        u64 cxy_ = mul2_(wx0, yp[0]);                                        \
        _Pragma("unroll")                                                    \
        for (int t = 1; t < 7; t++) {                                        \
            u64 wx = mul2_(w2[t], xp[t]);                                    \
            u64 wy = mul2_(w2[t], yp[t]);                                    \
            a_   = add2_(a_, wx);                                            \
            b_   = add2_(b_, wy);                                            \
            cxx_ = fma2_(wx, xp[t], cxx_);                                   \
            cyy_ = fma2_(wy, yp[t], cyy_);                                   \
            cxy_ = fma2_(wx, yp[t], cxy_);                                   \
        }                                                                    \
        Wx[(s)] = a_; Wy[(s)] = b_;                                          \
        Wxx[(s)] = cxx_; Wyy[(s)] = cyy_; Wxy[(s)] = cxy_;                   \
    }

#pragma unroll
    for (int r = 0; r < 6; r++) {
        HCONV(r, r);
    }

#pragma unroll
    for (int r = 6; r < TILE_H; r++) {
        if (r == ROWS_A) {                       // group B must be resident now
            asm volatile("cp.async.wait_group 0;");
            __syncthreads();
        }
        HCONV(r, r % 7);

        u64 mx  = mul2_(w2[0], Wx[(r - 6) % 7]);
        u64 my  = mul2_(w2[0], Wy[(r - 6) % 7]);
        u64 exx = mul2_(w2[0], Wxx[(r - 6) % 7]);
        u64 eyy = mul2_(w2[0], Wyy[(r - 6) % 7]);
        u64 exy = mul2_(w2[0], Wxy[(r - 6) % 7]);
#pragma unroll
        for (int t = 1; t < 7; t++) {
            int s = (r - 6 + t) % 7;
            mx  = fma2_(w2[t], Wx[s],  mx);
            my  = fma2_(w2[t], Wy[s],  my);
            exx = fma2_(w2[t], Wxx[s], exx);
            eyy = fma2_(w2[t], Wyy[s], eyy);
            exy = fma2_(w2[t], Wxy[s], exy);
        }

        u64 nmx = neg2_(mx);
        u64 sxx = fma2_(nmx, mx, exx);
        u64 syy = fma2_(neg2_(my), my, eyy);
        u64 sxy = fma2_(nmx, my, exy);

        u64 mxmy = mul2_(mx, my);
        u64 n1 = fma2_(two2, mxmy, c1_2);
        u64 n2 = fma2_(two2, sxy, c2_2);
        u64 num = mul2_(n1, n2);

        u64 myy = mul2_(my, my);
        u64 d1 = fma2_(mx, mx, myy);
        d1 = add2_(d1, c1_2);
        u64 d2 = add2_(add2_(sxx, syy), c2_2);
        u64 den = mul2_(d1, d2);

        float nlo, nhi, dlo, dhi;
        upk2(num, nlo, nhi);
        upk2(den, dlo, dhi);
        sum += __fdividef(nlo, dlo) + __fdividef(nhi, dhi);
    }
#undef HCONV

    // ---- block reduction ----
#pragma unroll
    for (int off = 16; off; off >>= 1)
        sum += __shfl_down_sync(0xffffffffu, sum, off);
    if ((tid & 31) == 0) wsum[tid >> 5] = sum;
    __syncthreads();

    // ---- last-block finalize (single-kernel) ----
    if (tid == 0) {
        float s = wsum[0] + wsum[1] + wsum[2] + wsum[3];
        atomicAdd(&g_acc, (double)s);
        __threadfence();
        unsigned t = atomicAdd(&g_tick, 1u);
        if (t == (unsigned)(nblocks - 1)) {
            double v = *(volatile double*)&g_acc;
            out[0] = (float)(v / ((double)BATCH * HH * WW));
            g_acc = 0.0;          // reset for next graph replay
            g_tick = 0;
            __threadfence();
        }
    }
}

extern "C" void kernel_launch(void* const* d_in, const int* in_sizes, int n_in,
                              void* d_out, int out_size)
{
    const float* x = (const float*)d_in[0];
    const float* y = (const float*)d_in[1];
    const float* k = (const float*)d_in[2];
    float* out = (float*)d_out;

    static int configured = 0;
    const int smem_bytes = 2 * TILE_H * SPITCH * (int)sizeof(float);
    if (!configured) {
        cudaFuncSetAttribute(ssim_main, cudaFuncAttributeMaxDynamicSharedMemorySize,
                             smem_bytes);
        configured = 1;
    }

    dim3 grid(WW / OUTW, HH / OUTH, BATCH);
    int nblocks = grid.x * grid.y * grid.z;
    ssim_main<<<grid, THREADS, smem_bytes>>>(x, y, k, out, nblocks);
}